// round 7
// baseline (speedup 1.0000x reference)
#include <cuda_runtime.h>
#include <cuda_fp16.h>
#include <cstdint>

// 4 convs (3x3,2x3,3x2,2x2) on x[16,512,32,32] -> interleave -> BN -> ReLU.
// mma.sync implicit GEMM (tcgen05 unavailable at plain sm_103 PTX target).
// R7: conv kernel templated on (KH,KW,conv) -> dj/di fully unrolled, no runtime
// div, ptxas can software-pipeline LDSM under HMMA across the whole stage.

#define NB 16

__device__ __half g_y[1024 * 16384];          // conv output [m][p], fp16
__device__ __half g_wp[9 * 1024 * 512];       // packed per-tap weights [tap][m][c]
__device__ __half g_xh[NB * 32 * 32 * 512];   // x NHWC fp16 [n][i][j][c]
__device__ float  g_bias[1024];
__device__ float  g_psum[1024 * 128];
__device__ float  g_qsum[1024 * 128];
__device__ float  g_scale[256];
__device__ float  g_shift[256];

// ---------------- pack weights: Wp[tap][m][c], tap = di*3+dj --------------------
__global__ void pack_weights_kernel(const float* __restrict__ w1, const float* __restrict__ w2,
                                    const float* __restrict__ w3, const float* __restrict__ w4) {
    int idx = blockIdx.x * 256 + threadIdx.x;
    if (idx >= 9 * 1024 * 512) return;
    int t   = idx / (1024 * 512);
    int rem = idx - t * (1024 * 512);
    int m = rem >> 9, c = rem & 511;
    int conv = m >> 8, co = m & 255;
    int di = t / 3, dj = t - di * 3;
    int kh = 3 - (conv & 1), kw = 3 - (conv >> 1);
    float v = 0.f;
    if (di < kh && dj < kw) {
        const float* w = (conv == 0) ? w1 : (conv == 1) ? w2 : (conv == 2) ? w3 : w4;
        v = w[((co * 512 + c) * kh + di) * kw + dj];
    }
    g_wp[((size_t)t * 1024 + m) * 512 + c] = __float2half(v);
}

__global__ void pack_misc_kernel(const float* __restrict__ b1, const float* __restrict__ b2,
                                 const float* __restrict__ b3, const float* __restrict__ b4) {
    int m = blockIdx.x * 256 + threadIdx.x;
    int conv = m >> 8, co = m & 255;
    const float* b = (conv == 0) ? b1 : (conv == 1) ? b2 : (conv == 2) ? b3 : b4;
    g_bias[m] = b[co];
}

// ---- NCHW fp32 -> NHWC fp16 (smem-tiled transpose) -----------------------------
__global__ void convert_x_kernel(const float* __restrict__ x) {
    __shared__ float tile[32][33];
    int ni = blockIdx.x;
    int c0 = blockIdx.y << 5;
    int n = ni >> 5, i = ni & 31;
    int tid = threadIdx.x;
    #pragma unroll
    for (int it = 0; it < 4; it++) {
        int cc = it * 8 + (tid >> 5);
        int j  = tid & 31;
        tile[cc][j] = x[(((size_t)n * 512 + c0 + cc) << 10) + (i << 5) + j];
    }
    __syncthreads();
    int j   = tid >> 3;
    int cc0 = (tid & 7) << 2;
    __half2 lo = __floats2half2_rn(tile[cc0][j], tile[cc0 + 1][j]);
    __half2 hi = __floats2half2_rn(tile[cc0 + 2][j], tile[cc0 + 3][j]);
    uint2 v = make_uint2(*(uint32_t*)&lo, *(uint32_t*)&hi);
    *reinterpret_cast<uint2*>(g_xh + ((((size_t)ni << 5) + j) << 9) + c0 + cc0) = v;
}

// ------------------------------- conv (implicit GEMM) ---------------------------
#define XS_STRIDE 40
#define XS_BUFB   17280
#define WS_OFF    (2 * XS_BUFB)
#define WS_SLOTB  30720
#define WS_TAPB   10240
#define SMEM_BYTES (2 * XS_BUFB + 2 * WS_SLOTB)

#define CP16(dst, src, sz) \
    asm volatile("cp.async.cg.shared.global [%0], [%1], 16, %2;" \
                 :: "r"(dst), "l"(src), "r"(sz))

template<int KH, int KW, int CONV>
__global__ void __launch_bounds__(256, 2) conv_kernel() {
    extern __shared__ __align__(128) unsigned char dsmem[];
    const uint32_t blob = (uint32_t)__cvta_generic_to_shared(dsmem);

    const int tid  = threadIdx.x;
    const int lane = tid & 31, warp = tid >> 5;
    const int r     = warp >> 1;           // pixel row 0..3
    const int nbase = (warp & 1) << 6;     // cout half
    const int m0   = ((CONV << 1) | blockIdx.y) << 7;
    const int pb = blockIdx.x;
    const int n  = pb >> 3;
    const int i0 = (pb & 7) << 2;

    const int la15 = lane & 15;
    const int lahi = (lane >> 4) << 3;
    const int bm   = (lane & 7) + ((lane >> 4) << 3);
    const int bk   = ((lane >> 3) & 1) << 3;

    float acc[2][8][4];
    #pragma unroll
    for (int a = 0; a < 2; a++)
        #pragma unroll
        for (int b = 0; b < 8; b++)
            #pragma unroll
            for (int c = 0; c < 4; c++) acc[a][b][c] = 0.f;

    auto issueXs = [&](int chunk) {        // 216 pixels x 4 segs, zero halo
        int c0 = chunk << 5;
        uint32_t xdst = blob + (chunk & 1) * XS_BUFB;
        #pragma unroll
        for (int it = 0; it < 4; it++) {
            int idx = it * 256 + tid;
            if (idx < 864) {
                int pixel = idx >> 2, seg = idx & 3;
                int rr = pixel / 36, col = pixel - rr * 36;
                int xi = i0 - 1 + rr, xj = col - 1;
                bool inb = ((unsigned)xi < 32u) & ((unsigned)xj < 32u);
                const __half* src = inb
                    ? g_xh + ((((size_t)(n * 32 + xi)) << 5) + xj) * 512 + c0 + (seg << 3)
                    : g_xh;
                CP16(xdst + (pixel * XS_STRIDE + (seg << 3)) * 2, src, inb ? 16 : 0);
            }
        }
    };
    auto issueWs = [&](int t, int chunk, int di) {   // all KW taps of row di
        int c0 = chunk << 5;
        uint32_t wdst = blob + WS_OFF + (t & 1) * WS_SLOTB;
        constexpr int total = KW << 9;               // KW*128*4
        #pragma unroll
        for (int it = 0; it < (total + 255) / 256; it++) {
            int idx = it * 256 + tid;
            if (total % 256 == 0 || idx < total) {
                int dj  = idx >> 9;
                int rem = idx & 511;
                int mm = rem >> 2, seg = rem & 3;
                const __half* wsrc =
                    g_wp + (((size_t)(dj + di * 3) * 1024 + m0 + mm) << 9) + c0;
                CP16(wdst + dj * WS_TAPB + (mm * XS_STRIDE + (seg << 3)) * 2,
                     wsrc + (seg << 3), 16);
            }
        }
    };

    issueXs(0); issueWs(0, 0, 0);
    asm volatile("cp.async.commit_group;");

    #pragma unroll 1
    for (int chunk = 0; chunk < 16; chunk++) {
        const uint32_t xb = blob + (chunk & 1) * XS_BUFB;
        #pragma unroll
        for (int di = 0; di < KH; di++) {
            const int t = chunk * KH + di;
            asm volatile("cp.async.wait_group 0;");
            __syncthreads();
            if (di == 0 && chunk + 1 < 16) issueXs(chunk + 1);
            if (t + 1 < 16 * KH) {
                int nt_ = t + 1;
                int nc = (di + 1 == KH) ? chunk + 1 : chunk;
                int nd = (di + 1 == KH) ? 0 : di + 1;
                issueWs(nt_, nc, nd);
            }
            asm volatile("cp.async.commit_group;");

            const uint32_t wbase = blob + WS_OFF + (t & 1) * WS_SLOTB;
            const int prow = r + di;

            #pragma unroll
            for (int dj = 0; dj < KW; dj++) {
                const uint32_t wb = wbase + dj * WS_TAPB;
                #pragma unroll
                for (int ks = 0; ks < 32; ks += 16) {
                    uint32_t a[2][4], b[4][4];
                    #pragma unroll
                    for (int mt = 0; mt < 2; mt++) {
                        uint32_t addr = xb +
                            (((prow * 36 + mt * 16 + la15 + dj) * XS_STRIDE) + ks + lahi) * 2;
                        asm volatile(
                            "ldmatrix.sync.aligned.m8n8.x4.shared.b16 {%0,%1,%2,%3}, [%4];"
                            : "=r"(a[mt][0]), "=r"(a[mt][1]), "=r"(a[mt][2]), "=r"(a[mt][3])
                            : "r"(addr));
                    }
                    #pragma unroll
                    for (int g = 0; g < 4; g++) {
                        uint32_t addr = wb + (((nbase + g * 16 + bm) * XS_STRIDE) + ks + bk) * 2;
                        asm volatile(
                            "ldmatrix.sync.aligned.m8n8.x4.shared.b16 {%0,%1,%2,%3}, [%4];"
                            : "=r"(b[g][0]), "=r"(b[g][1]), "=r"(b[g][2]), "=r"(b[g][3])
                            : "r"(addr));
                    }
                    #pragma unroll
                    for (int mt = 0; mt < 2; mt++)
                        #pragma unroll
                        for (int nt = 0; nt < 8; nt++) {
                            asm volatile(
                                "mma.sync.aligned.m16n8k16.row.col.f32.f16.f16.f32 "
                                "{%0,%1,%2,%3}, {%4,%5,%6,%7}, {%8,%9}, {%0,%1,%2,%3};"
                                : "+f"(acc[mt][nt][0]), "+f"(acc[mt][nt][1]),
                                  "+f"(acc[mt][nt][2]), "+f"(acc[mt][nt][3])
                                : "r"(a[mt][0]), "r"(a[mt][1]), "r"(a[mt][2]), "r"(a[mt][3]),
                                  "r"(b[nt >> 1][(nt & 1) * 2]),
                                  "r"(b[nt >> 1][(nt & 1) * 2 + 1]));
                        }
                }
            }
        }
    }

    __syncthreads();   // smem -> BN partial staging reuse

    // ---- epilogue: bias, y(fp16), deterministic BN partials ----
    float* s_ps = reinterpret_cast<float*>(dsmem);         // [4][128]
    float* s_qs = reinterpret_cast<float*>(dsmem) + 512;   // [4][128]
    const int pbase = (n << 10) + ((i0 + r) << 5);
    const int pc = pbase + (lane >> 2);
    #pragma unroll
    for (int nt = 0; nt < 8; nt++) {
        int cl = nbase + nt * 8 + ((lane & 3) << 1);
        int mg = m0 + cl;
        float b0 = g_bias[mg], b1 = g_bias[mg + 1];
        float s0 = 0.f, q0 = 0.f, s1 = 0.f, q1 = 0.f;
        __half* y0 = g_y + (size_t)mg * 16384;
        __half* y1 = y0 + 16384;
        #pragma unroll
        for (int mt = 0; mt < 2; mt++) {
            int p = pc + mt * 16;
            float v00 = acc[mt][nt][0] + b0;
            float v01 = acc[mt][nt][1] + b1;
            float v10 = acc[mt][nt][2] + b0;
            float v11 = acc[mt][nt][3] + b1;
            y0[p]     = __float2half(v00);  y1[p]     = __float2half(v01);
            y0[p + 8] = __float2half(v10);  y1[p + 8] = __float2half(v11);
            s0 += v00 + v10;  q0 += v00 * v00 + v10 * v10;
            s1 += v01 + v11;  q1 += v01 * v01 + v11 * v11;
        }
        #pragma unroll
        for (int off = 4; off <= 16; off <<= 1) {
            s0 += __shfl_xor_sync(0xffffffffu, s0, off);
            q0 += __shfl_xor_sync(0xffffffffu, q0, off);
            s1 += __shfl_xor_sync(0xffffffffu, s1, off);
            q1 += __shfl_xor_sync(0xffffffffu, q1, off);
        }
        if (lane < 4) {
            s_ps[r * 128 + cl]     = s0;  s_qs[r * 128 + cl]     = q0;
            s_ps[r * 128 + cl + 1] = s1;  s_qs[r * 128 + cl + 1] = q1;
        }
    }
    __syncthreads();
    if (tid < 128) {
        float s = s_ps[tid] + s_ps[128 + tid] + s_ps[256 + tid] + s_ps[384 + tid];
        float q = s_qs[tid] + s_qs[128 + tid] + s_qs[256 + tid] + s_qs[384 + tid];
        g_psum[(size_t)(m0 + tid) * 128 + pb] = s;
        g_qsum[(size_t)(m0 + tid) * 128 + pb] = q;
    }
}

// ---------------- BN stats ------------------------------------------------------
__global__ void stats_kernel(const float* __restrict__ gamma, const float* __restrict__ beta) {
    __shared__ float sh_s[128], sh_q[128];
    int co = blockIdx.x;
    int t  = threadIdx.x;
    float s = 0.f, q = 0.f;
    #pragma unroll
    for (int conv = 0; conv < 4; conv++) {
        size_t base = (size_t)(conv * 256 + co) * 128 + t;
        s += g_psum[base];
        q += g_qsum[base];
    }
    sh_s[t] = s; sh_q[t] = q;
    __syncthreads();
    for (int off = 64; off >= 32; off >>= 1) {
        if (t < off) { sh_s[t] += sh_s[t + off]; sh_q[t] += sh_q[t + off]; }
        __syncthreads();
    }
    if (t < 32) {
        s = sh_s[t]; q = sh_q[t];
        #pragma unroll
        for (int off = 16; off >= 1; off >>= 1) {
            s += __shfl_xor_sync(0xffffffffu, s, off);
            q += __shfl_xor_sync(0xffffffffu, q, off);
        }
        if (t == 0) {
            float mean = s * (1.f / 65536.f);
            float var  = q * (1.f / 65536.f) - mean * mean;
            float sc   = gamma[co] * rsqrtf(var + 1e-5f);
            g_scale[co] = sc;
            g_shift[co] = beta[co] - mean * sc;
        }
    }
}

// ------------- BN apply + ReLU + pixel-shuffle interleave -----------------------
__global__ void bn_kernel(float* __restrict__ out) {
    int o4 = blockIdx.x * 256 + threadIdx.x;
    int o  = o4 << 2;
    int J  = o & 63;
    int I  = (o >> 6) & 63;
    int co = (o >> 12) & 255;
    int n  = o >> 20;
    int convA = (I & 1);
    int convB = (I & 1) | 2;
    int p = (n << 10) + ((I >> 1) << 5) + (J >> 1);
    const __half* ya = g_y + (size_t)((convA << 8) | co) * 16384 + p;
    const __half* yb = g_y + (size_t)((convB << 8) | co) * 16384 + p;
    __half2 a2 = *reinterpret_cast<const __half2*>(ya);
    __half2 b2 = *reinterpret_cast<const __half2*>(yb);
    float sa = g_scale[co], sha = g_shift[co];
    float4 r;
    r.x = fmaxf(__half2float(a2.x) * sa + sha, 0.f);
    r.y = fmaxf(__half2float(b2.x) * sa + sha, 0.f);
    r.z = fmaxf(__half2float(a2.y) * sa + sha, 0.f);
    r.w = fmaxf(__half2float(b2.y) * sa + sha, 0.f);
    reinterpret_cast<float4*>(out)[o4] = r;
}

// --------------------------------- launch ---------------------------------------
extern "C" void kernel_launch(void* const* d_in, const int* in_sizes, int n_in,
                              void* d_out, int out_size) {
    const float* x     = (const float*)d_in[0];
    const float* w1    = (const float*)d_in[1];
    const float* b1    = (const float*)d_in[2];
    const float* w2    = (const float*)d_in[3];
    const float* b2    = (const float*)d_in[4];
    const float* w3    = (const float*)d_in[5];
    const float* b3    = (const float*)d_in[6];
    const float* w4    = (const float*)d_in[7];
    const float* b4    = (const float*)d_in[8];
    const float* gamma = (const float*)d_in[9];
    const float* beta  = (const float*)d_in[10];
    float* out = (float*)d_out;

    static bool attr_set = false;
    if (!attr_set) {
        cudaFuncSetAttribute(conv_kernel<3,3,0>, cudaFuncAttributeMaxDynamicSharedMemorySize, SMEM_BYTES);
        cudaFuncSetAttribute(conv_kernel<2,3,1>, cudaFuncAttributeMaxDynamicSharedMemorySize, SMEM_BYTES);
        cudaFuncSetAttribute(conv_kernel<3,2,2>, cudaFuncAttributeMaxDynamicSharedMemorySize, SMEM_BYTES);
        cudaFuncSetAttribute(conv_kernel<2,2,3>, cudaFuncAttributeMaxDynamicSharedMemorySize, SMEM_BYTES);
        attr_set = true;
    }

    pack_weights_kernel<<<(9 * 1024 * 512 + 255) / 256, 256>>>(w1, w2, w3, w4);
    pack_misc_kernel<<<4, 256>>>(b1, b2, b3, b4);
    {
        dim3 g(512, 16);
        convert_x_kernel<<<g, 256>>>(x);
    }
    {
        dim3 grid(128, 2);
        conv_kernel<3,3,0><<<grid, 256, SMEM_BYTES>>>();
        conv_kernel<2,3,1><<<grid, 256, SMEM_BYTES>>>();
        conv_kernel<3,2,2><<<grid, 256, SMEM_BYTES>>>();
        conv_kernel<2,2,3><<<grid, 256, SMEM_BYTES>>>();
    }
    stats_kernel<<<256, 128>>>(gamma, beta);
    bn_kernel<<<(16777216 / 4) / 256, 256>>>(out);
}

// round 8
// speedup vs baseline: 1.1453x; 1.1453x over previous
#include <cuda_runtime.h>
#include <cuda_fp16.h>
#include <cstdint>

// 4 convs (3x3,2x3,3x2,2x2) on x[16,512,32,32] -> interleave -> BN -> ReLU.
// mma.sync implicit GEMM. R8: ONE launch grid=(128,8); block-granular dispatch to
// fully specialized conv bodies (compile-time KH/KW unroll, no runtime div).

#define NB 16

__device__ __half g_y[1024 * 16384];          // conv output [m][p], fp16
__device__ __half g_wp[9 * 1024 * 512];       // packed per-tap weights [tap][m][c]
__device__ __half g_xh[NB * 32 * 32 * 512];   // x NHWC fp16 [n][i][j][c]
__device__ float  g_bias[1024];
__device__ float  g_psum[1024 * 128];
__device__ float  g_qsum[1024 * 128];
__device__ float  g_scale[256];
__device__ float  g_shift[256];

// ---------------- pack weights: Wp[tap][m][c], tap = di*3+dj --------------------
__global__ void pack_weights_kernel(const float* __restrict__ w1, const float* __restrict__ w2,
                                    const float* __restrict__ w3, const float* __restrict__ w4) {
    int idx = blockIdx.x * 256 + threadIdx.x;
    if (idx >= 9 * 1024 * 512) return;
    int t   = idx / (1024 * 512);
    int rem = idx - t * (1024 * 512);
    int m = rem >> 9, c = rem & 511;
    int conv = m >> 8, co = m & 255;
    int di = t / 3, dj = t - di * 3;
    int kh = 3 - (conv & 1), kw = 3 - (conv >> 1);
    float v = 0.f;
    if (di < kh && dj < kw) {
        const float* w = (conv == 0) ? w1 : (conv == 1) ? w2 : (conv == 2) ? w3 : w4;
        v = w[((co * 512 + c) * kh + di) * kw + dj];
    }
    g_wp[((size_t)t * 1024 + m) * 512 + c] = __float2half(v);
}

__global__ void pack_misc_kernel(const float* __restrict__ b1, const float* __restrict__ b2,
                                 const float* __restrict__ b3, const float* __restrict__ b4) {
    int m = blockIdx.x * 256 + threadIdx.x;
    int conv = m >> 8, co = m & 255;
    const float* b = (conv == 0) ? b1 : (conv == 1) ? b2 : (conv == 2) ? b3 : b4;
    g_bias[m] = b[co];
}

// ---- NCHW fp32 -> NHWC fp16 (smem-tiled transpose) -----------------------------
__global__ void convert_x_kernel(const float* __restrict__ x) {
    __shared__ float tile[32][33];
    int ni = blockIdx.x;
    int c0 = blockIdx.y << 5;
    int n = ni >> 5, i = ni & 31;
    int tid = threadIdx.x;
    #pragma unroll
    for (int it = 0; it < 4; it++) {
        int cc = it * 8 + (tid >> 5);
        int j  = tid & 31;
        tile[cc][j] = x[(((size_t)n * 512 + c0 + cc) << 10) + (i << 5) + j];
    }
    __syncthreads();
    int j   = tid >> 3;
    int cc0 = (tid & 7) << 2;
    __half2 lo = __floats2half2_rn(tile[cc0][j], tile[cc0 + 1][j]);
    __half2 hi = __floats2half2_rn(tile[cc0 + 2][j], tile[cc0 + 3][j]);
    uint2 v = make_uint2(*(uint32_t*)&lo, *(uint32_t*)&hi);
    *reinterpret_cast<uint2*>(g_xh + ((((size_t)ni << 5) + j) << 9) + c0 + cc0) = v;
}

// ------------------------------- conv (implicit GEMM) ---------------------------
#define XS_STRIDE 40
#define XS_BUFB   17280
#define WS_OFF    (2 * XS_BUFB)
#define WS_SLOTB  30720
#define WS_TAPB   10240
#define SMEM_BYTES (2 * XS_BUFB + 2 * WS_SLOTB)

#define CP16(dst, src, sz) \
    asm volatile("cp.async.cg.shared.global [%0], [%1], 16, %2;" \
                 :: "r"(dst), "l"(src), "r"(sz))

template<int KH, int KW>
__device__ __forceinline__ void conv_body(unsigned char* dsmem, int m0) {
    const uint32_t blob = (uint32_t)__cvta_generic_to_shared(dsmem);

    const int tid  = threadIdx.x;
    const int lane = tid & 31, warp = tid >> 5;
    const int r     = warp >> 1;           // pixel row 0..3
    const int nbase = (warp & 1) << 6;     // cout half
    const int pb = blockIdx.x;
    const int n  = pb >> 3;
    const int i0 = (pb & 7) << 2;

    const int la15 = lane & 15;
    const int lahi = (lane >> 4) << 3;
    const int bm   = (lane & 7) + ((lane >> 4) << 3);
    const int bk   = ((lane >> 3) & 1) << 3;

    float acc[2][8][4];
    #pragma unroll
    for (int a = 0; a < 2; a++)
        #pragma unroll
        for (int b = 0; b < 8; b++)
            #pragma unroll
            for (int c = 0; c < 4; c++) acc[a][b][c] = 0.f;

    auto issueXs = [&](int chunk) {        // 216 pixels x 4 segs, zero halo
        int c0 = chunk << 5;
        uint32_t xdst = blob + (chunk & 1) * XS_BUFB;
        #pragma unroll
        for (int it = 0; it < 4; it++) {
            int idx = it * 256 + tid;
            if (idx < 864) {
                int pixel = idx >> 2, seg = idx & 3;
                int rr = pixel / 36, col = pixel - rr * 36;
                int xi = i0 - 1 + rr, xj = col - 1;
                bool inb = ((unsigned)xi < 32u) & ((unsigned)xj < 32u);
                const __half* src = inb
                    ? g_xh + ((((size_t)(n * 32 + xi)) << 5) + xj) * 512 + c0 + (seg << 3)
                    : g_xh;
                CP16(xdst + (pixel * XS_STRIDE + (seg << 3)) * 2, src, inb ? 16 : 0);
            }
        }
    };
    auto issueWs = [&](int t, int chunk, int di) {   // all KW taps of row di
        int c0 = chunk << 5;
        uint32_t wdst = blob + WS_OFF + (t & 1) * WS_SLOTB;
        constexpr int total = KW << 9;               // KW*128*4
        #pragma unroll
        for (int it = 0; it < (total + 255) / 256; it++) {
            int idx = it * 256 + tid;
            if (total % 256 == 0 || idx < total) {
                int dj  = idx >> 9;
                int rem = idx & 511;
                int mm = rem >> 2, seg = rem & 3;
                const __half* wsrc =
                    g_wp + (((size_t)(dj + di * 3) * 1024 + m0 + mm) << 9) + c0;
                CP16(wdst + dj * WS_TAPB + (mm * XS_STRIDE + (seg << 3)) * 2,
                     wsrc + (seg << 3), 16);
            }
        }
    };

    issueXs(0); issueWs(0, 0, 0);
    asm volatile("cp.async.commit_group;");

    #pragma unroll 1
    for (int chunk = 0; chunk < 16; chunk++) {
        const uint32_t xb = blob + (chunk & 1) * XS_BUFB;
        #pragma unroll
        for (int di = 0; di < KH; di++) {
            const int t = chunk * KH + di;
            asm volatile("cp.async.wait_group 0;");
            __syncthreads();
            if (di == 0 && chunk + 1 < 16) issueXs(chunk + 1);
            if (t + 1 < 16 * KH) {
                int nt_ = t + 1;
                int nc = (di + 1 == KH) ? chunk + 1 : chunk;
                int nd = (di + 1 == KH) ? 0 : di + 1;
                issueWs(nt_, nc, nd);
            }
            asm volatile("cp.async.commit_group;");

            const uint32_t wbase = blob + WS_OFF + (t & 1) * WS_SLOTB;
            const int prow = r + di;

            #pragma unroll
            for (int dj = 0; dj < KW; dj++) {
                const uint32_t wb = wbase + dj * WS_TAPB;
                #pragma unroll
                for (int ks = 0; ks < 32; ks += 16) {
                    uint32_t a[2][4], b[4][4];
                    #pragma unroll
                    for (int mt = 0; mt < 2; mt++) {
                        uint32_t addr = xb +
                            (((prow * 36 + mt * 16 + la15 + dj) * XS_STRIDE) + ks + lahi) * 2;
                        asm volatile(
                            "ldmatrix.sync.aligned.m8n8.x4.shared.b16 {%0,%1,%2,%3}, [%4];"
                            : "=r"(a[mt][0]), "=r"(a[mt][1]), "=r"(a[mt][2]), "=r"(a[mt][3])
                            : "r"(addr));
                    }
                    #pragma unroll
                    for (int g = 0; g < 4; g++) {
                        uint32_t addr = wb + (((nbase + g * 16 + bm) * XS_STRIDE) + ks + bk) * 2;
                        asm volatile(
                            "ldmatrix.sync.aligned.m8n8.x4.shared.b16 {%0,%1,%2,%3}, [%4];"
                            : "=r"(b[g][0]), "=r"(b[g][1]), "=r"(b[g][2]), "=r"(b[g][3])
                            : "r"(addr));
                    }
                    #pragma unroll
                    for (int mt = 0; mt < 2; mt++)
                        #pragma unroll
                        for (int nt = 0; nt < 8; nt++) {
                            asm volatile(
                                "mma.sync.aligned.m16n8k16.row.col.f32.f16.f16.f32 "
                                "{%0,%1,%2,%3}, {%4,%5,%6,%7}, {%8,%9}, {%0,%1,%2,%3};"
                                : "+f"(acc[mt][nt][0]), "+f"(acc[mt][nt][1]),
                                  "+f"(acc[mt][nt][2]), "+f"(acc[mt][nt][3])
                                : "r"(a[mt][0]), "r"(a[mt][1]), "r"(a[mt][2]), "r"(a[mt][3]),
                                  "r"(b[nt >> 1][(nt & 1) * 2]),
                                  "r"(b[nt >> 1][(nt & 1) * 2 + 1]));
                        }
                }
            }
        }
    }

    __syncthreads();   // smem -> BN partial staging reuse

    // ---- epilogue: bias, y(fp16), deterministic BN partials ----
    float* s_ps = reinterpret_cast<float*>(dsmem);         // [4][128]
    float* s_qs = reinterpret_cast<float*>(dsmem) + 512;   // [4][128]
    const int pbase = (n << 10) + ((i0 + r) << 5);
    const int pc = pbase + (lane >> 2);
    #pragma unroll
    for (int nt = 0; nt < 8; nt++) {
        int cl = nbase + nt * 8 + ((lane & 3) << 1);
        int mg = m0 + cl;
        float b0 = g_bias[mg], b1 = g_bias[mg + 1];
        float s0 = 0.f, q0 = 0.f, s1 = 0.f, q1 = 0.f;
        __half* y0 = g_y + (size_t)mg * 16384;
        __half* y1 = y0 + 16384;
        #pragma unroll
        for (int mt = 0; mt < 2; mt++) {
            int p = pc + mt * 16;
            float v00 = acc[mt][nt][0] + b0;
            float v01 = acc[mt][nt][1] + b1;
            float v10 = acc[mt][nt][2] + b0;
            float v11 = acc[mt][nt][3] + b1;
            y0[p]     = __float2half(v00);  y1[p]     = __float2half(v01);
            y0[p + 8] = __float2half(v10);  y1[p + 8] = __float2half(v11);
            s0 += v00 + v10;  q0 += v00 * v00 + v10 * v10;
            s1 += v01 + v11;  q1 += v01 * v01 + v11 * v11;
        }
        #pragma unroll
        for (int off = 4; off <= 16; off <<= 1) {
            s0 += __shfl_xor_sync(0xffffffffu, s0, off);
            q0 += __shfl_xor_sync(0xffffffffu, q0, off);
            s1 += __shfl_xor_sync(0xffffffffu, s1, off);
            q1 += __shfl_xor_sync(0xffffffffu, q1, off);
        }
        if (lane < 4) {
            s_ps[r * 128 + cl]     = s0;  s_qs[r * 128 + cl]     = q0;
            s_ps[r * 128 + cl + 1] = s1;  s_qs[r * 128 + cl + 1] = q1;
        }
    }
    __syncthreads();
    if (tid < 128) {
        float s = s_ps[tid] + s_ps[128 + tid] + s_ps[256 + tid] + s_ps[384 + tid];
        float q = s_qs[tid] + s_qs[128 + tid] + s_qs[256 + tid] + s_qs[384 + tid];
        g_psum[(size_t)(m0 + tid) * 128 + pb] = s;
        g_qsum[(size_t)(m0 + tid) * 128 + pb] = q;
    }
}

__global__ void __launch_bounds__(256, 2) conv_kernel() {
    extern __shared__ __align__(128) unsigned char dsmem[];
    const int m0 = blockIdx.y << 7;
    switch (blockIdx.y >> 1) {
        case 0: conv_body<3, 3>(dsmem, m0); break;
        case 1: conv_body<2, 3>(dsmem, m0); break;
        case 2: conv_body<3, 2>(dsmem, m0); break;
        default: conv_body<2, 2>(dsmem, m0); break;
    }
}

// ---------------- BN stats ------------------------------------------------------
__global__ void stats_kernel(const float* __restrict__ gamma, const float* __restrict__ beta) {
    __shared__ float sh_s[128], sh_q[128];
    int co = blockIdx.x;
    int t  = threadIdx.x;
    float s = 0.f, q = 0.f;
    #pragma unroll
    for (int conv = 0; conv < 4; conv++) {
        size_t base = (size_t)(conv * 256 + co) * 128 + t;
        s += g_psum[base];
        q += g_qsum[base];
    }
    sh_s[t] = s; sh_q[t] = q;
    __syncthreads();
    for (int off = 64; off >= 32; off >>= 1) {
        if (t < off) { sh_s[t] += sh_s[t + off]; sh_q[t] += sh_q[t + off]; }
        __syncthreads();
    }
    if (t < 32) {
        s = sh_s[t]; q = sh_q[t];
        #pragma unroll
        for (int off = 16; off >= 1; off >>= 1) {
            s += __shfl_xor_sync(0xffffffffu, s, off);
            q += __shfl_xor_sync(0xffffffffu, q, off);
        }
        if (t == 0) {
            float mean = s * (1.f / 65536.f);
            float var  = q * (1.f / 65536.f) - mean * mean;
            float sc   = gamma[co] * rsqrtf(var + 1e-5f);
            g_scale[co] = sc;
            g_shift[co] = beta[co] - mean * sc;
        }
    }
}

// ------------- BN apply + ReLU + pixel-shuffle interleave -----------------------
__global__ void bn_kernel(float* __restrict__ out) {
    int o4 = blockIdx.x * 256 + threadIdx.x;
    int o  = o4 << 2;
    int J  = o & 63;
    int I  = (o >> 6) & 63;
    int co = (o >> 12) & 255;
    int n  = o >> 20;
    int convA = (I & 1);
    int convB = (I & 1) | 2;
    int p = (n << 10) + ((I >> 1) << 5) + (J >> 1);
    const __half* ya = g_y + (size_t)((convA << 8) | co) * 16384 + p;
    const __half* yb = g_y + (size_t)((convB << 8) | co) * 16384 + p;
    __half2 a2 = *reinterpret_cast<const __half2*>(ya);
    __half2 b2 = *reinterpret_cast<const __half2*>(yb);
    float sa = g_scale[co], sha = g_shift[co];
    float4 r;
    r.x = fmaxf(__half2float(a2.x) * sa + sha, 0.f);
    r.y = fmaxf(__half2float(b2.x) * sa + sha, 0.f);
    r.z = fmaxf(__half2float(a2.y) * sa + sha, 0.f);
    r.w = fmaxf(__half2float(b2.y) * sa + sha, 0.f);
    reinterpret_cast<float4*>(out)[o4] = r;
}

// --------------------------------- launch ---------------------------------------
extern "C" void kernel_launch(void* const* d_in, const int* in_sizes, int n_in,
                              void* d_out, int out_size) {
    const float* x     = (const float*)d_in[0];
    const float* w1    = (const float*)d_in[1];
    const float* b1    = (const float*)d_in[2];
    const float* w2    = (const float*)d_in[3];
    const float* b2    = (const float*)d_in[4];
    const float* w3    = (const float*)d_in[5];
    const float* b3    = (const float*)d_in[6];
    const float* w4    = (const float*)d_in[7];
    const float* b4    = (const float*)d_in[8];
    const float* gamma = (const float*)d_in[9];
    const float* beta  = (const float*)d_in[10];
    float* out = (float*)d_out;

    static bool attr_set = false;
    if (!attr_set) {
        cudaFuncSetAttribute(conv_kernel, cudaFuncAttributeMaxDynamicSharedMemorySize, SMEM_BYTES);
        attr_set = true;
    }

    pack_weights_kernel<<<(9 * 1024 * 512 + 255) / 256, 256>>>(w1, w2, w3, w4);
    pack_misc_kernel<<<4, 256>>>(b1, b2, b3, b4);
    {
        dim3 g(512, 16);
        convert_x_kernel<<<g, 256>>>(x);
    }
    {
        dim3 grid(128, 8);
        conv_kernel<<<grid, 256, SMEM_BYTES>>>();
    }
    stats_kernel<<<256, 128>>>(gamma, beta);
    bn_kernel<<<(16777216 / 4) / 256, 256>>>(out);
}